// round 13
// baseline (speedup 1.0000x reference)
#include <cuda_runtime.h>
#include <cuda_bf16.h>
#include <math.h>
#include <stdint.h>

#define N_NODES 10000
#define N_PAD   10112              /* 79 * 128 */
#define N_EDGES 160000
#define HIDDEN  256
#define HEADS   8
#define HEAD_DIM 32
#define LN_EPS  1e-5f
#define ATTN_SCALE 0.17677669529663687f  /* 1/sqrt(32) */

// ---------------- scratch (device globals; no allocation allowed) ------------
__device__ float g_Q[N_NODES * HIDDEN];
__device__ float g_K[N_NODES * HIDDEN];
__device__ float g_V[N_NODES * HIDDEN];
__device__ float g_tmp[N_NODES * HIDDEN];
__device__ int   g_cnt[N_NODES];
__device__ int   g_cursor[N_NODES];
__device__ int   g_off[N_NODES + 1];
__device__ int   g_bucket[N_EDGES];

// pre-split bf16 operands
__device__ __nv_bfloat16 g_Xhi[N_PAD * HIDDEN];
__device__ __nv_bfloat16 g_Xlo[N_PAD * HIDDEN];
__device__ __nv_bfloat16 g_AGhi[N_PAD * HIDDEN];
__device__ __nv_bfloat16 g_AGlo[N_PAD * HIDDEN];
__device__ __nv_bfloat16 g_WhiT[4][HIDDEN * HIDDEN];  // n-major [n][k]
__device__ __nv_bfloat16 g_WloT[4][HIDDEN * HIDDEN];

__device__ __forceinline__ void split2(float x, __nv_bfloat16& hi, __nv_bfloat16& lo) {
    hi = __float2bfloat16(x);
    lo = __float2bfloat16(x - __bfloat162float(hi));
}

// ---------------- CSR build --------------------------------------------------
__global__ void k_count(const int* __restrict__ ei) {
    int e = blockIdx.x * blockDim.x + threadIdx.x;
    if (e < N_EDGES) atomicAdd(&g_cnt[ei[e]], 1);
}

// shuffle-based block scan: 1024 threads x 10 elements, 2 barriers
__global__ void k_scan() {
    __shared__ int wsum[32];
    const int t = threadIdx.x;
    const int lane = t & 31;
    const int warp = t >> 5;
    const int base = t * 10;

    int loc[10];
    int s = 0;
    #pragma unroll
    for (int i = 0; i < 10; i++) {
        int idx = base + i;
        loc[i] = (idx < N_NODES) ? g_cnt[idx] : 0;
        s += loc[i];
    }

    int v = s;
    #pragma unroll
    for (int o = 1; o < 32; o <<= 1) {
        int u = __shfl_up_sync(0xffffffffu, v, o);
        if (lane >= o) v += u;
    }
    if (lane == 31) wsum[warp] = v;
    __syncthreads();
    if (warp == 0) {
        int w = wsum[lane];
        #pragma unroll
        for (int o = 1; o < 32; o <<= 1) {
            int u = __shfl_up_sync(0xffffffffu, w, o);
            if (lane >= o) w += u;
        }
        wsum[lane] = w;
    }
    __syncthreads();

    int run = v - s + (warp > 0 ? wsum[warp - 1] : 0);
    #pragma unroll
    for (int i = 0; i < 10; i++) {
        int idx = base + i;
        if (idx < N_NODES) {
            g_off[idx] = run;
            run += loc[i];
        }
    }
    if (t == 1023) g_off[N_NODES] = run;
}

__global__ void k_scatter(const int* __restrict__ ei) {
    int e = blockIdx.x * blockDim.x + threadIdx.x;
    if (e < N_EDGES) {
        int src = ei[e];
        int dst = ei[N_EDGES + e];
        int pos = g_off[src] + atomicAdd(&g_cursor[src], 1);
        g_bucket[pos] = dst;
    }
}

// ---------------- pre-split kernels ------------------------------------------
__global__ void k_split_X(const float* __restrict__ X) {
    int idx = blockIdx.x * blockDim.x + threadIdx.x;
    int row = idx >> 6;
    int c4 = idx & 63;
    if (row >= N_PAD) return;
    float4 x = make_float4(0.f, 0.f, 0.f, 0.f);
    if (row < N_NODES) x = *(const float4*)&X[row * HIDDEN + c4 * 4];
    __nv_bfloat16 h0, h1, h2, h3, l0, l1, l2, l3;
    split2(x.x, h0, l0); split2(x.y, h1, l1);
    split2(x.z, h2, l2); split2(x.w, h3, l3);
    __nv_bfloat162 hp0 = {h0, h1}, hp1 = {h2, h3};
    __nv_bfloat162 lp0 = {l0, l1}, lp1 = {l2, l3};
    uint2 hv = make_uint2(*(uint32_t*)&hp0, *(uint32_t*)&hp1);
    uint2 lv = make_uint2(*(uint32_t*)&lp0, *(uint32_t*)&lp1);
    *(uint2*)&g_Xhi[row * HIDDEN + c4 * 4] = hv;
    *(uint2*)&g_Xlo[row * HIDDEN + c4 * 4] = lv;
    if (row >= N_NODES) {
        uint2 z = make_uint2(0u, 0u);
        *(uint2*)&g_AGhi[row * HIDDEN + c4 * 4] = z;
        *(uint2*)&g_AGlo[row * HIDDEN + c4 * 4] = z;
    }
}

__global__ void k_split_W(const float* __restrict__ Wq, const float* __restrict__ Wk,
                          const float* __restrict__ Wv, const float* __restrict__ Wo) {
    const int z = blockIdx.z;
    const float* W = (z == 0) ? Wq : (z == 1) ? Wk : (z == 2) ? Wv : Wo;
    __shared__ float tile[32][33];
    const int tx = threadIdx.x;
    const int ty = threadIdx.y;
    const int kb = blockIdx.y * 32;
    const int nb = blockIdx.x * 32;
    #pragma unroll
    for (int i = 0; i < 4; i++)
        tile[ty + i * 8][tx] = W[(kb + ty + i * 8) * HIDDEN + nb + tx];
    __syncthreads();
    #pragma unroll
    for (int i = 0; i < 4; i++) {
        float x = tile[tx][ty + i * 8];
        __nv_bfloat16 hi, lo;
        split2(x, hi, lo);
        g_WhiT[z][(nb + ty + i * 8) * HIDDEN + kb + tx] = hi;
        g_WloT[z][(nb + ty + i * 8) * HIDDEN + kb + tx] = lo;
    }
}

// ===== HMMA split-bf16 GEMM: KC=32 double-buffered cp.async pipeline =========
// smem row layout (128B): [hi 64B | lo 64B], SW128 swizzle.
#define TM 128
#define TN 128
#define KC 32
#define NCHUNK (HIDDEN / KC)   // 8

#define STAGE_BYTES 32768      // A(16KB) + B(16KB)
#define SM_B_OFF    16384
#define SM_TOTAL    65536

#define SWZ(x) ((x) ^ (((x) >> 3) & 0x70))

__device__ __forceinline__ uint32_t smem_u32(const void* p) {
    uint32_t a;
    asm("{ .reg .u64 t; cvta.to.shared.u64 t, %1; cvt.u32.u64 %0, t; }"
        : "=r"(a) : "l"(p));
    return a;
}

__device__ __forceinline__ void cpa16(uint32_t saddr, const void* gaddr) {
    asm volatile("cp.async.cg.shared.global [%0], [%1], 16;"
                 :: "r"(saddr), "l"(gaddr));
}

__device__ __forceinline__ void ldsm4(uint32_t& r0, uint32_t& r1,
                                      uint32_t& r2, uint32_t& r3, uint32_t addr) {
    asm volatile("ldmatrix.sync.aligned.m8n8.x4.shared.b16 {%0,%1,%2,%3}, [%4];"
                 : "=r"(r0), "=r"(r1), "=r"(r2), "=r"(r3) : "r"(addr));
}

__device__ __forceinline__ void mma_bf16(float* d, const uint32_t* a,
                                         uint32_t b0, uint32_t b1) {
    asm volatile(
        "mma.sync.aligned.m16n8k16.row.col.f32.bf16.bf16.f32 "
        "{%0,%1,%2,%3}, {%4,%5,%6,%7}, {%8,%9}, {%0,%1,%2,%3};"
        : "+f"(d[0]), "+f"(d[1]), "+f"(d[2]), "+f"(d[3])
        : "r"(a[0]), "r"(a[1]), "r"(a[2]), "r"(a[3]), "r"(b0), "r"(b1));
}

// stage one K-chunk (A hi/lo + B hi/lo) into smem stage s
__device__ __forceinline__ void stage_load(
    uint32_t sbase, int s, int kt, int tid, int rowBase, int colBase,
    const __nv_bfloat16* __restrict__ Ahi, const __nv_bfloat16* __restrict__ Alo,
    const __nv_bfloat16* __restrict__ Bhi, const __nv_bfloat16* __restrict__ Blo) {
    const uint32_t stbase = sbase + (uint32_t)s * STAGE_BYTES;
    #pragma unroll
    for (int i = 0; i < 8; i++) {
        int idx = i * 256 + tid;       // 0..2047
        int mat = idx >> 10;           // 0 = A, 1 = B
        int u   = idx & 1023;
        int row = u >> 3;              // 0..127
        int j   = u & 7;               // 16B unit; j<4 -> hi, j>=4 -> lo
        uint32_t soff = SWZ((uint32_t)(row * 128 + j * 16));
        const __nv_bfloat16* src;
        if (mat == 0)
            src = ((j < 4) ? Ahi : Alo) + (rowBase + row) * HIDDEN + kt + (j & 3) * 8;
        else
            src = ((j < 4) ? Bhi : Blo) + (colBase + row) * HIDDEN + kt + (j & 3) * 8;
        cpa16(stbase + (mat ? SM_B_OFF : 0) + soff, src);
    }
    asm volatile("cp.async.commit_group;");
}

__device__ __forceinline__ void gemm_body(const __nv_bfloat16* __restrict__ Ahi,
                                          const __nv_bfloat16* __restrict__ Alo,
                                          const __nv_bfloat16* __restrict__ Bhi,
                                          const __nv_bfloat16* __restrict__ Blo,
                                          float* __restrict__ C) {
    __shared__ char smem[SM_TOTAL];
    const uint32_t sbase = smem_u32(smem);
    const int tid = threadIdx.x;        // 256
    const int wid = tid >> 5;
    const int lane = tid & 31;
    const int rowBase = blockIdx.x * TM;
    const int colBase = blockIdx.y * TN;
    const int warp_m = wid & 1;
    const int warp_n = wid >> 1;

    float acc[4][4][4];
    #pragma unroll
    for (int i = 0; i < 4; i++)
        #pragma unroll
        for (int j = 0; j < 4; j++)
            #pragma unroll
            for (int r = 0; r < 4; r++) acc[i][j][r] = 0.f;

    const int lrow = lane & 15;
    const int lkoff = (lane >> 4) * 8;

    // prefetch chunk 0
    stage_load(sbase, 0, 0, tid, rowBase, colBase, Ahi, Alo, Bhi, Blo);

    for (int c = 0; c < NCHUNK; c++) {
        if (c + 1 < NCHUNK)
            stage_load(sbase, (c + 1) & 1, (c + 1) * KC, tid, rowBase, colBase,
                       Ahi, Alo, Bhi, Blo);

        if (c + 1 < NCHUNK)
            asm volatile("cp.async.wait_group 1;");
        else
            asm volatile("cp.async.wait_group 0;");
        __syncthreads();

        const uint32_t stbase = sbase + (uint32_t)(c & 1) * STAGE_BYTES;

        #pragma unroll
        for (int ks = 0; ks < 2; ks++) {
            const int kcol = ks * 16 + lkoff;         // 0..24
            uint32_t bHi[2][4], bLo[2][4];
            #pragma unroll
            for (int np = 0; np < 2; np++) {
                int n = warp_n * 32 + np * 16 + lrow;
                uint32_t hioff = SWZ((uint32_t)(n * 128 + kcol * 2));
                uint32_t looff = SWZ((uint32_t)(n * 128 + 64 + kcol * 2));
                ldsm4(bHi[np][0], bHi[np][1], bHi[np][2], bHi[np][3],
                      stbase + SM_B_OFF + hioff);
                ldsm4(bLo[np][0], bLo[np][1], bLo[np][2], bLo[np][3],
                      stbase + SM_B_OFF + looff);
            }
            #pragma unroll
            for (int mt = 0; mt < 4; mt++) {
                uint32_t aHi[4], aLo[4];
                int row = warp_m * 64 + mt * 16 + lrow;
                uint32_t hioff = SWZ((uint32_t)(row * 128 + kcol * 2));
                uint32_t looff = SWZ((uint32_t)(row * 128 + 64 + kcol * 2));
                ldsm4(aHi[0], aHi[1], aHi[2], aHi[3], stbase + hioff);
                ldsm4(aLo[0], aLo[1], aLo[2], aLo[3], stbase + looff);
                #pragma unroll
                for (int np = 0; np < 2; np++) {
                    #pragma unroll
                    for (int h = 0; h < 2; h++) {
                        int nt = np * 2 + h;
                        mma_bf16(acc[mt][nt], aHi, bHi[np][h], bHi[np][h + 2]);
                        mma_bf16(acc[mt][nt], aHi, bLo[np][h], bLo[np][h + 2]);
                        mma_bf16(acc[mt][nt], aLo, bHi[np][h], bHi[np][h + 2]);
                    }
                }
            }
        }
        __syncthreads();   // stage (c&1) free for prefetch of chunk c+2
    }

    const int crow0 = rowBase + warp_m * 64 + (lane >> 2);
    const int ccol0 = colBase + warp_n * 32 + (lane & 3) * 2;
    #pragma unroll
    for (int mt = 0; mt < 4; mt++) {
        #pragma unroll
        for (int nt = 0; nt < 4; nt++) {
            int r0 = crow0 + mt * 16;
            int cc = ccol0 + nt * 8;
            if (r0 < N_NODES)
                *(float2*)&C[r0 * HIDDEN + cc] = make_float2(acc[mt][nt][0], acc[mt][nt][1]);
            if (r0 + 8 < N_NODES)
                *(float2*)&C[(r0 + 8) * HIDDEN + cc] = make_float2(acc[mt][nt][2], acc[mt][nt][3]);
        }
    }
}

__global__ void __launch_bounds__(256, 2)
k_qkv_mma() {
    float* C = (blockIdx.z == 0) ? g_Q : (blockIdx.z == 1) ? g_K : g_V;
    gemm_body(g_Xhi, g_Xlo, g_WhiT[blockIdx.z], g_WloT[blockIdx.z], C);
}

__global__ void __launch_bounds__(256, 2)
k_out_mma() {
    gemm_body(g_AGhi, g_AGlo, g_WhiT[3], g_WloT[3], g_tmp);
}

// ---------------- edge attention ---------------------------------------------
__global__ void k_attn() {
    const int n = blockIdx.x;
    const int h = threadIdx.x >> 5;
    const int lane = threadIdx.x & 31;
    const int g = lane >> 3;
    const int sl = lane & 7;

    const int beg = g_off[n];
    const int end = g_off[n + 1];
    const int iters = (end - beg + 3) >> 2;

    const float4 q = __ldg((const float4*)&g_Q[n * HIDDEN + h * HEAD_DIM + sl * 4]);

    float d = 0.f;
    float4 acc = make_float4(0.f, 0.f, 0.f, 0.f);

    for (int it = 0; it < iters; it++) {
        int i = beg + it * 4 + g;
        bool valid = (i < end);
        int dst = valid ? __ldg(&g_bucket[i]) : 0;
        const float4 k4 = __ldg((const float4*)&g_K[dst * HIDDEN + h * HEAD_DIM + sl * 4]);
        float s = q.x * k4.x + q.y * k4.y + q.z * k4.z + q.w * k4.w;
        s += __shfl_xor_sync(0xffffffffu, s, 1);
        s += __shfl_xor_sync(0xffffffffu, s, 2);
        s += __shfl_xor_sync(0xffffffffu, s, 4);
        float p = valid ? __expf(s * ATTN_SCALE) : 0.f;
        const float4 v4 = __ldg((const float4*)&g_V[dst * HIDDEN + h * HEAD_DIM + sl * 4]);
        d += p;
        acc.x = fmaf(p, v4.x, acc.x);
        acc.y = fmaf(p, v4.y, acc.y);
        acc.z = fmaf(p, v4.z, acc.z);
        acc.w = fmaf(p, v4.w, acc.w);
    }

    d += __shfl_xor_sync(0xffffffffu, d, 8);
    d += __shfl_xor_sync(0xffffffffu, d, 16);
    acc.x += __shfl_xor_sync(0xffffffffu, acc.x, 8);
    acc.x += __shfl_xor_sync(0xffffffffu, acc.x, 16);
    acc.y += __shfl_xor_sync(0xffffffffu, acc.y, 8);
    acc.y += __shfl_xor_sync(0xffffffffu, acc.y, 16);
    acc.z += __shfl_xor_sync(0xffffffffu, acc.z, 8);
    acc.z += __shfl_xor_sync(0xffffffffu, acc.z, 16);
    acc.w += __shfl_xor_sync(0xffffffffu, acc.w, 8);
    acc.w += __shfl_xor_sync(0xffffffffu, acc.w, 16);

    if (g == 0) {
        float inv = (d > 0.f) ? (1.0f / d) : 0.f;
        float r[4] = {acc.x * inv, acc.y * inv, acc.z * inv, acc.w * inv};
        __nv_bfloat16 hi[4], lo[4];
        #pragma unroll
        for (int j = 0; j < 4; j++) split2(r[j], hi[j], lo[j]);
        __nv_bfloat162 hp0 = {hi[0], hi[1]}, hp1 = {hi[2], hi[3]};
        __nv_bfloat162 lp0 = {lo[0], lo[1]}, lp1 = {lo[2], lo[3]};
        uint2 hv = make_uint2(*(uint32_t*)&hp0, *(uint32_t*)&hp1);
        uint2 lv = make_uint2(*(uint32_t*)&lp0, *(uint32_t*)&lp1);
        *(uint2*)&g_AGhi[n * HIDDEN + h * HEAD_DIM + sl * 4] = hv;
        *(uint2*)&g_AGlo[n * HIDDEN + h * HEAD_DIM + sl * 4] = lv;
    }
}

// ---------------- residual + layernorm ---------------------------------------
__global__ void k_ln(const float* __restrict__ X,
                     const float* __restrict__ gamma,
                     const float* __restrict__ beta,
                     float* __restrict__ out) {
    const int n = blockIdx.x;
    const int t = threadIdx.x;
    __shared__ float red1[8];
    __shared__ float red2[8];

    float x = g_tmp[n * HIDDEN + t] + X[n * HIDDEN + t];

    float s = x;
    #pragma unroll
    for (int o = 16; o; o >>= 1) s += __shfl_xor_sync(0xffffffffu, s, o);
    if ((t & 31) == 0) red1[t >> 5] = s;
    __syncthreads();
    float mu;
    {
        float tot = 0.f;
        #pragma unroll
        for (int i = 0; i < 8; i++) tot += red1[i];
        mu = tot * (1.0f / HIDDEN);
    }

    float dx = x - mu;
    float v = dx * dx;
    #pragma unroll
    for (int o = 16; o; o >>= 1) v += __shfl_xor_sync(0xffffffffu, v, o);
    if ((t & 31) == 0) red2[t >> 5] = v;
    __syncthreads();
    float var;
    {
        float tot = 0.f;
        #pragma unroll
        for (int i = 0; i < 8; i++) tot += red2[i];
        var = tot * (1.0f / HIDDEN);
    }

    out[n * HIDDEN + t] = dx * rsqrtf(var + LN_EPS) * gamma[t] + beta[t];
}

// ---------------- launch ------------------------------------------------------
extern "C" void kernel_launch(void* const* d_in, const int* in_sizes, int n_in,
                              void* d_out, int out_size) {
    const float* X     = (const float*)d_in[0];
    const int*   ei    = (const int*)d_in[1];
    const float* Wq    = (const float*)d_in[2];
    const float* Wk    = (const float*)d_in[3];
    const float* Wv    = (const float*)d_in[4];
    const float* Wo    = (const float*)d_in[5];
    const float* gamma = (const float*)d_in[6];
    const float* beta  = (const float*)d_in[7];
    float* out = (float*)d_out;

    static void* p_cnt = nullptr;
    static void* p_cursor = nullptr;
    static cudaStream_t s2 = nullptr;
    static cudaEvent_t evFork = nullptr, evJoin = nullptr;
    if (!p_cnt) {
        cudaGetSymbolAddress(&p_cnt, g_cnt);
        cudaGetSymbolAddress(&p_cursor, g_cursor);
        cudaStreamCreateWithFlags(&s2, cudaStreamNonBlocking);
        cudaEventCreateWithFlags(&evFork, cudaEventDisableTiming);
        cudaEventCreateWithFlags(&evJoin, cudaEventDisableTiming);
    }

    cudaMemsetAsync(p_cnt, 0, N_NODES * sizeof(int));       // launch 1
    cudaMemsetAsync(p_cursor, 0, N_NODES * sizeof(int));    // launch 2

    cudaEventRecord(evFork, 0);
    cudaStreamWaitEvent(s2, evFork, 0);

    k_count<<<(N_EDGES + 255) / 256, 256, 0, s2>>>(ei);      // launch 3

    k_split_X<<<(N_PAD * 64 + 255) / 256, 256>>>(X);         // launch 4
    dim3 gw(8, 8, 4);
    k_split_W<<<gw, dim3(32, 8)>>>(Wq, Wk, Wv, Wo);          // launch 5

    dim3 gq(N_PAD / TM, HIDDEN / TN, 3);
    k_qkv_mma<<<gq, 256>>>();                                // launch 6 <- profiled

    k_scan<<<1, 1024, 0, s2>>>();                            // launch 7 (s2)
    k_scatter<<<(N_EDGES + 255) / 256, 256, 0, s2>>>(ei);    // launch 8 (s2)
    cudaEventRecord(evJoin, s2);

    cudaStreamWaitEvent(0, evJoin, 0);
    k_attn<<<N_NODES, 256>>>();                              // launch 9

    dim3 go(N_PAD / TM, HIDDEN / TN, 1);
    k_out_mma<<<go, 256>>>();                                // launch 10

    k_ln<<<N_NODES, 256>>>(X, gamma, beta, out);             // launch 11
}

// round 17
// speedup vs baseline: 1.0780x; 1.0780x over previous
#include <cuda_runtime.h>
#include <cuda_bf16.h>
#include <math.h>
#include <stdint.h>

#define N_NODES 10000
#define N_PAD   10112              /* 79 * 128 */
#define N_EDGES 160000
#define HIDDEN  256
#define HEADS   8
#define HEAD_DIM 32
#define LN_EPS  1e-5f
#define ATTN_SCALE 0.17677669529663687f  /* 1/sqrt(32) */

// ---------------- scratch (device globals; no allocation allowed) ------------
__device__ float g_Q[N_NODES * HIDDEN];
__device__ float g_K[N_NODES * HIDDEN];
__device__ float g_V[N_NODES * HIDDEN];
__device__ float g_tmp[N_NODES * HIDDEN];
__device__ int   g_cnt[N_NODES];      // zero-init; re-zeroed at graph tail
__device__ int   g_cursor[N_NODES];   // zero-init; re-zeroed at graph tail
__device__ int   g_off[N_NODES + 1];
__device__ int   g_bucket[N_EDGES];

// pre-split bf16 operands
__device__ __nv_bfloat16 g_Xhi[N_PAD * HIDDEN];
__device__ __nv_bfloat16 g_Xlo[N_PAD * HIDDEN];
__device__ __nv_bfloat16 g_AGhi[N_PAD * HIDDEN];
__device__ __nv_bfloat16 g_AGlo[N_PAD * HIDDEN];
__device__ __nv_bfloat16 g_WhiT[4][HIDDEN * HIDDEN];  // n-major [n][k]
__device__ __nv_bfloat16 g_WloT[4][HIDDEN * HIDDEN];

__device__ __forceinline__ void split2(float x, __nv_bfloat16& hi, __nv_bfloat16& lo) {
    hi = __float2bfloat16(x);
    lo = __float2bfloat16(x - __bfloat162float(hi));
}

// ---------------- CSR build --------------------------------------------------
__global__ void k_count(const int* __restrict__ ei) {
    int e = blockIdx.x * blockDim.x + threadIdx.x;
    if (e < N_EDGES) atomicAdd(&g_cnt[ei[e]], 1);
}

// shuffle-based block scan: 1024 threads x 10 elements, 2 barriers
__global__ void k_scan() {
    __shared__ int wsum[32];
    const int t = threadIdx.x;
    const int lane = t & 31;
    const int warp = t >> 5;
    const int base = t * 10;

    int loc[10];
    int s = 0;
    #pragma unroll
    for (int i = 0; i < 10; i++) {
        int idx = base + i;
        loc[i] = (idx < N_NODES) ? g_cnt[idx] : 0;
        s += loc[i];
    }

    int v = s;
    #pragma unroll
    for (int o = 1; o < 32; o <<= 1) {
        int u = __shfl_up_sync(0xffffffffu, v, o);
        if (lane >= o) v += u;
    }
    if (lane == 31) wsum[warp] = v;
    __syncthreads();
    if (warp == 0) {
        int w = wsum[lane];
        #pragma unroll
        for (int o = 1; o < 32; o <<= 1) {
            int u = __shfl_up_sync(0xffffffffu, w, o);
            if (lane >= o) w += u;
        }
        wsum[lane] = w;
    }
    __syncthreads();

    int run = v - s + (warp > 0 ? wsum[warp - 1] : 0);
    #pragma unroll
    for (int i = 0; i < 10; i++) {
        int idx = base + i;
        if (idx < N_NODES) {
            g_off[idx] = run;
            run += loc[i];
        }
    }
    if (t == 1023) g_off[N_NODES] = run;
}

__global__ void k_scatter(const int* __restrict__ ei) {
    int e = blockIdx.x * blockDim.x + threadIdx.x;
    if (e < N_EDGES) {
        int src = ei[e];
        int dst = ei[N_EDGES + e];
        int pos = g_off[src] + atomicAdd(&g_cursor[src], 1);
        g_bucket[pos] = dst;
    }
}

// ---------------- fused pre-split kernel (X part + W part) --------------------
#define SPLITX_BLOCKS ((N_PAD * 64 + 255) / 256)   /* 2528 */

__global__ void k_split(const float* __restrict__ X,
                        const float* __restrict__ Wq, const float* __restrict__ Wk,
                        const float* __restrict__ Wv, const float* __restrict__ Wo) {
    const int tid = threadIdx.x;
    if (blockIdx.x < SPLITX_BLOCKS) {
        // ---- X -> Xhi/Xlo (+ zero AG pad rows) ----
        int idx = blockIdx.x * 256 + tid;
        int row = idx >> 6;
        int c4 = idx & 63;
        if (row >= N_PAD) return;
        float4 x = make_float4(0.f, 0.f, 0.f, 0.f);
        if (row < N_NODES) x = *(const float4*)&X[row * HIDDEN + c4 * 4];
        __nv_bfloat16 h0, h1, h2, h3, l0, l1, l2, l3;
        split2(x.x, h0, l0); split2(x.y, h1, l1);
        split2(x.z, h2, l2); split2(x.w, h3, l3);
        __nv_bfloat162 hp0 = {h0, h1}, hp1 = {h2, h3};
        __nv_bfloat162 lp0 = {l0, l1}, lp1 = {l2, l3};
        uint2 hv = make_uint2(*(uint32_t*)&hp0, *(uint32_t*)&hp1);
        uint2 lv = make_uint2(*(uint32_t*)&lp0, *(uint32_t*)&lp1);
        *(uint2*)&g_Xhi[row * HIDDEN + c4 * 4] = hv;
        *(uint2*)&g_Xlo[row * HIDDEN + c4 * 4] = lv;
        if (row >= N_NODES) {
            uint2 z = make_uint2(0u, 0u);
            *(uint2*)&g_AGhi[row * HIDDEN + c4 * 4] = z;
            *(uint2*)&g_AGlo[row * HIDDEN + c4 * 4] = z;
        }
    } else {
        // ---- W[k][n] -> WT[n][k] split (tiled transpose) ----
        int b = blockIdx.x - SPLITX_BLOCKS;     // 0..255
        const int z = b >> 6;
        const int r = b & 63;
        const int nb = (r & 7) * 32;
        const int kb = (r >> 3) * 32;
        const float* W = (z == 0) ? Wq : (z == 1) ? Wk : (z == 2) ? Wv : Wo;
        __shared__ float tile[32][33];
        const int tx = tid & 31;
        const int ty = tid >> 5;    // 0..7
        #pragma unroll
        for (int i = 0; i < 4; i++)
            tile[ty + i * 8][tx] = W[(kb + ty + i * 8) * HIDDEN + nb + tx];
        __syncthreads();
        #pragma unroll
        for (int i = 0; i < 4; i++) {
            float x = tile[tx][ty + i * 8];
            __nv_bfloat16 hi, lo;
            split2(x, hi, lo);
            g_WhiT[z][(nb + ty + i * 8) * HIDDEN + kb + tx] = hi;
            g_WloT[z][(nb + ty + i * 8) * HIDDEN + kb + tx] = lo;
        }
    }
}

// ===== HMMA split-bf16 GEMM (round-10 validated: KC=64, 2 blocks/SM) =========
#define TM 128
#define TN 128
#define KC 64
#define NCHUNK (HIDDEN / KC)   // 4

#define SM_AHI 0
#define SM_ALO 16384
#define SM_BHI 32768
#define SM_BLO 49152
#define SM_TOTAL 65536

#define SWZ(x) ((x) ^ (((x) >> 3) & 0x70))

__device__ __forceinline__ uint32_t smem_u32(const void* p) {
    uint32_t a;
    asm("{ .reg .u64 t; cvta.to.shared.u64 t, %1; cvt.u32.u64 %0, t; }"
        : "=r"(a) : "l"(p));
    return a;
}

__device__ __forceinline__ void cpa16(uint32_t saddr, const void* gaddr) {
    asm volatile("cp.async.cg.shared.global [%0], [%1], 16;"
                 :: "r"(saddr), "l"(gaddr));
}

__device__ __forceinline__ void ldsm4(uint32_t& r0, uint32_t& r1,
                                      uint32_t& r2, uint32_t& r3, uint32_t addr) {
    asm volatile("ldmatrix.sync.aligned.m8n8.x4.shared.b16 {%0,%1,%2,%3}, [%4];"
                 : "=r"(r0), "=r"(r1), "=r"(r2), "=r"(r3) : "r"(addr));
}

__device__ __forceinline__ void mma_bf16(float* d, const uint32_t* a,
                                         uint32_t b0, uint32_t b1) {
    asm volatile(
        "mma.sync.aligned.m16n8k16.row.col.f32.bf16.bf16.f32 "
        "{%0,%1,%2,%3}, {%4,%5,%6,%7}, {%8,%9}, {%0,%1,%2,%3};"
        : "+f"(d[0]), "+f"(d[1]), "+f"(d[2]), "+f"(d[3])
        : "r"(a[0]), "r"(a[1]), "r"(a[2]), "r"(a[3]), "r"(b0), "r"(b1));
}

__device__ __forceinline__ void gemm_body(const __nv_bfloat16* __restrict__ Ahi,
                                          const __nv_bfloat16* __restrict__ Alo,
                                          const __nv_bfloat16* __restrict__ Bhi,
                                          const __nv_bfloat16* __restrict__ Blo,
                                          float* __restrict__ C) {
    __shared__ char smem[SM_TOTAL];
    const uint32_t sbase = smem_u32(smem);
    const int tid = threadIdx.x;        // 256
    const int wid = tid >> 5;
    const int lane = tid & 31;
    const int rowBase = blockIdx.x * TM;
    const int colBase = blockIdx.y * TN;
    const int warp_m = wid & 1;
    const int warp_n = wid >> 1;

    float acc[4][4][4];
    #pragma unroll
    for (int i = 0; i < 4; i++)
        #pragma unroll
        for (int j = 0; j < 4; j++)
            #pragma unroll
            for (int r = 0; r < 4; r++) acc[i][j][r] = 0.f;

    const int lrow = lane & 15;
    const int lkoff = (lane >> 4) * 8;

    for (int c = 0; c < NCHUNK; c++) {
        const int kt = c * KC;

        #pragma unroll
        for (int i = 0; i < 4; i++) {
            int idx = i * 256 + tid;    // 0..1023
            int row = idx >> 3;         // 0..127
            int j = idx & 7;            // 16B unit within 128B row
            uint32_t soff = SWZ((uint32_t)(row * 128 + j * 16));
            cpa16(sbase + SM_AHI + soff, Ahi + (rowBase + row) * HIDDEN + kt + j * 8);
            cpa16(sbase + SM_ALO + soff, Alo + (rowBase + row) * HIDDEN + kt + j * 8);
            cpa16(sbase + SM_BHI + soff, Bhi + (colBase + row) * HIDDEN + kt + j * 8);
            cpa16(sbase + SM_BLO + soff, Blo + (colBase + row) * HIDDEN + kt + j * 8);
        }
        asm volatile("cp.async.commit_group;");
        asm volatile("cp.async.wait_group 0;");
        __syncthreads();

        #pragma unroll
        for (int ks = 0; ks < 4; ks++) {
            const int kcol = ks * 16 + lkoff;
            uint32_t bHi[2][4], bLo[2][4];
            #pragma unroll
            for (int np = 0; np < 2; np++) {
                int n = warp_n * 32 + np * 16 + lrow;
                uint32_t off = SWZ((uint32_t)(n * 128 + kcol * 2));
                ldsm4(bHi[np][0], bHi[np][1], bHi[np][2], bHi[np][3],
                      sbase + SM_BHI + off);
                ldsm4(bLo[np][0], bLo[np][1], bLo[np][2], bLo[np][3],
                      sbase + SM_BLO + off);
            }
            #pragma unroll
            for (int mt = 0; mt < 4; mt++) {
                uint32_t aHi[4], aLo[4];
                int row = warp_m * 64 + mt * 16 + lrow;
                uint32_t off = SWZ((uint32_t)(row * 128 + kcol * 2));
                ldsm4(aHi[0], aHi[1], aHi[2], aHi[3], sbase + SM_AHI + off);
                ldsm4(aLo[0], aLo[1], aLo[2], aLo[3], sbase + SM_ALO + off);
                #pragma unroll
                for (int np = 0; np < 2; np++) {
                    #pragma unroll
                    for (int h = 0; h < 2; h++) {
                        int nt = np * 2 + h;
                        mma_bf16(acc[mt][nt], aHi, bHi[np][h], bHi[np][h + 2]);
                        mma_bf16(acc[mt][nt], aHi, bLo[np][h], bLo[np][h + 2]);
                        mma_bf16(acc[mt][nt], aLo, bHi[np][h], bHi[np][h + 2]);
                    }
                }
            }
        }
        __syncthreads();
    }

    const int crow0 = rowBase + warp_m * 64 + (lane >> 2);
    const int ccol0 = colBase + warp_n * 32 + (lane & 3) * 2;
    #pragma unroll
    for (int mt = 0; mt < 4; mt++) {
        #pragma unroll
        for (int nt = 0; nt < 4; nt++) {
            int r0 = crow0 + mt * 16;
            int cc = ccol0 + nt * 8;
            if (r0 < N_NODES)
                *(float2*)&C[r0 * HIDDEN + cc] = make_float2(acc[mt][nt][0], acc[mt][nt][1]);
            if (r0 + 8 < N_NODES)
                *(float2*)&C[(r0 + 8) * HIDDEN + cc] = make_float2(acc[mt][nt][2], acc[mt][nt][3]);
        }
    }
}

__global__ void __launch_bounds__(256, 2)
k_qkv_mma() {
    float* C = (blockIdx.z == 0) ? g_Q : (blockIdx.z == 1) ? g_K : g_V;
    gemm_body(g_Xhi, g_Xlo, g_WhiT[blockIdx.z], g_WloT[blockIdx.z], C);
}

__global__ void __launch_bounds__(256, 2)
k_out_mma() {
    gemm_body(g_AGhi, g_AGlo, g_WhiT[3], g_WloT[3], g_tmp);
}

// ---------------- edge attention ---------------------------------------------
__global__ void k_attn() {
    const int n = blockIdx.x;
    const int h = threadIdx.x >> 5;
    const int lane = threadIdx.x & 31;
    const int g = lane >> 3;
    const int sl = lane & 7;

    const int beg = g_off[n];
    const int end = g_off[n + 1];
    const int iters = (end - beg + 3) >> 2;

    const float4 q = __ldg((const float4*)&g_Q[n * HIDDEN + h * HEAD_DIM + sl * 4]);

    float d = 0.f;
    float4 acc = make_float4(0.f, 0.f, 0.f, 0.f);

    for (int it = 0; it < iters; it++) {
        int i = beg + it * 4 + g;
        bool valid = (i < end);
        int dst = valid ? __ldg(&g_bucket[i]) : 0;
        const float4 k4 = __ldg((const float4*)&g_K[dst * HIDDEN + h * HEAD_DIM + sl * 4]);
        float s = q.x * k4.x + q.y * k4.y + q.z * k4.z + q.w * k4.w;
        s += __shfl_xor_sync(0xffffffffu, s, 1);
        s += __shfl_xor_sync(0xffffffffu, s, 2);
        s += __shfl_xor_sync(0xffffffffu, s, 4);
        float p = valid ? __expf(s * ATTN_SCALE) : 0.f;
        const float4 v4 = __ldg((const float4*)&g_V[dst * HIDDEN + h * HEAD_DIM + sl * 4]);
        d += p;
        acc.x = fmaf(p, v4.x, acc.x);
        acc.y = fmaf(p, v4.y, acc.y);
        acc.z = fmaf(p, v4.z, acc.z);
        acc.w = fmaf(p, v4.w, acc.w);
    }

    d += __shfl_xor_sync(0xffffffffu, d, 8);
    d += __shfl_xor_sync(0xffffffffu, d, 16);
    acc.x += __shfl_xor_sync(0xffffffffu, acc.x, 8);
    acc.x += __shfl_xor_sync(0xffffffffu, acc.x, 16);
    acc.y += __shfl_xor_sync(0xffffffffu, acc.y, 8);
    acc.y += __shfl_xor_sync(0xffffffffu, acc.y, 16);
    acc.z += __shfl_xor_sync(0xffffffffu, acc.z, 8);
    acc.z += __shfl_xor_sync(0xffffffffu, acc.z, 16);
    acc.w += __shfl_xor_sync(0xffffffffu, acc.w, 8);
    acc.w += __shfl_xor_sync(0xffffffffu, acc.w, 16);

    if (g == 0) {
        float inv = (d > 0.f) ? (1.0f / d) : 0.f;
        float r[4] = {acc.x * inv, acc.y * inv, acc.z * inv, acc.w * inv};
        __nv_bfloat16 hi[4], lo[4];
        #pragma unroll
        for (int j = 0; j < 4; j++) split2(r[j], hi[j], lo[j]);
        __nv_bfloat162 hp0 = {hi[0], hi[1]}, hp1 = {hi[2], hi[3]};
        __nv_bfloat162 lp0 = {lo[0], lo[1]}, lp1 = {lo[2], lo[3]};
        uint2 hv = make_uint2(*(uint32_t*)&hp0, *(uint32_t*)&hp1);
        uint2 lv = make_uint2(*(uint32_t*)&lp0, *(uint32_t*)&lp1);
        *(uint2*)&g_AGhi[n * HIDDEN + h * HEAD_DIM + sl * 4] = hv;
        *(uint2*)&g_AGlo[n * HIDDEN + h * HEAD_DIM + sl * 4] = lv;
    }
}

// ---------------- residual + layernorm ---------------------------------------
__global__ void k_ln(const float* __restrict__ X,
                     const float* __restrict__ gamma,
                     const float* __restrict__ beta,
                     float* __restrict__ out) {
    const int n = blockIdx.x;
    const int t = threadIdx.x;
    __shared__ float red1[8];
    __shared__ float red2[8];

    float x = g_tmp[n * HIDDEN + t] + X[n * HIDDEN + t];

    float s = x;
    #pragma unroll
    for (int o = 16; o; o >>= 1) s += __shfl_xor_sync(0xffffffffu, s, o);
    if ((t & 31) == 0) red1[t >> 5] = s;
    __syncthreads();
    float mu;
    {
        float tot = 0.f;
        #pragma unroll
        for (int i = 0; i < 8; i++) tot += red1[i];
        mu = tot * (1.0f / HIDDEN);
    }

    float dx = x - mu;
    float v = dx * dx;
    #pragma unroll
    for (int o = 16; o; o >>= 1) v += __shfl_xor_sync(0xffffffffu, v, o);
    if ((t & 31) == 0) red2[t >> 5] = v;
    __syncthreads();
    float var;
    {
        float tot = 0.f;
        #pragma unroll
        for (int i = 0; i < 8; i++) tot += red2[i];
        var = tot * (1.0f / HIDDEN);
    }

    out[n * HIDDEN + t] = dx * rsqrtf(var + LN_EPS) * gamma[t] + beta[t];
}

// ---------------- launch ------------------------------------------------------
extern "C" void kernel_launch(void* const* d_in, const int* in_sizes, int n_in,
                              void* d_out, int out_size) {
    const float* X     = (const float*)d_in[0];
    const int*   ei    = (const int*)d_in[1];
    const float* Wq    = (const float*)d_in[2];
    const float* Wk    = (const float*)d_in[3];
    const float* Wv    = (const float*)d_in[4];
    const float* Wo    = (const float*)d_in[5];
    const float* gamma = (const float*)d_in[6];
    const float* beta  = (const float*)d_in[7];
    float* out = (float*)d_out;

    static void* p_cnt = nullptr;
    static void* p_cursor = nullptr;
    static cudaStream_t s2 = nullptr;
    static cudaEvent_t evFork = nullptr, evJoin = nullptr, evEnd = nullptr;
    if (!p_cnt) {
        cudaGetSymbolAddress(&p_cnt, g_cnt);
        cudaGetSymbolAddress(&p_cursor, g_cursor);
        cudaStreamCreateWithFlags(&s2, cudaStreamNonBlocking);
        cudaEventCreateWithFlags(&evFork, cudaEventDisableTiming);
        cudaEventCreateWithFlags(&evJoin, cudaEventDisableTiming);
        cudaEventCreateWithFlags(&evEnd, cudaEventDisableTiming);
    }

    // fork s2 from main for capture reachability
    cudaEventRecord(evFork, 0);
    cudaStreamWaitEvent(s2, evFork, 0);

    // CSR chain on s2 (g_cnt/g_cursor are zero from init / previous replay tail)
    k_count<<<(N_EDGES + 255) / 256, 256, 0, s2>>>(ei);      // launch 1
    k_scan<<<1, 1024, 0, s2>>>();                            // launch 2
    k_scatter<<<(N_EDGES + 255) / 256, 256, 0, s2>>>(ei);    // launch 3
    cudaEventRecord(evJoin, s2);

    // split + QKV on main, concurrent with CSR chain
    k_split<<<SPLITX_BLOCKS + 256, 256>>>(X, Wq, Wk, Wv, Wo);  // launch 4
    dim3 gq(N_PAD / TM, HIDDEN / TN, 3);
    k_qkv_mma<<<gq, 256>>>();                                // launch 5

    // join, then attention (profiled: launch 6)
    cudaStreamWaitEvent(0, evJoin, 0);
    k_attn<<<N_NODES, 256>>>();                              // launch 6 <- profiled

    // tail-zero CSR counters for the NEXT replay (on s2, overlaps attn/out)
    cudaMemsetAsync(p_cnt, 0, N_NODES * sizeof(int), s2);    // launch 7
    cudaMemsetAsync(p_cursor, 0, N_NODES * sizeof(int), s2); // launch 8
    cudaEventRecord(evEnd, s2);

    dim3 go(N_PAD / TM, HIDDEN / TN, 1);
    k_out_mma<<<go, 256>>>();                                // launch 9

    k_ln<<<N_NODES, 256>>>(X, gamma, beta, out);             // launch 10

    // join s2 back before capture ends
    cudaStreamWaitEvent(0, evEnd, 0);
}